// round 9
// baseline (speedup 1.0000x reference)
#include <cuda_runtime.h>
#include <math.h>

#define EPSF 1e-4f
typedef unsigned long long u64;

__device__ __forceinline__ u64 pack2(float x){
  u64 r; unsigned xi = __float_as_uint(x);
  asm("mov.b64 %0, {%1, %1};" : "=l"(r) : "r"(xi));
  return r;
}
__device__ __forceinline__ void fma2(u64 &acc, u64 a, u64 b){
  asm("fma.rn.f32x2 %0, %1, %2, %0;" : "+l"(acc) : "l"(a), "l"(b));
}
__device__ __forceinline__ float2 unpack2(u64 v){
  unsigned lo, hi;
  asm("mov.b64 {%0, %1}, %2;" : "=r"(lo), "=r"(hi) : "l"(v));
  return make_float2(__uint_as_float(lo), __uint_as_float(hi));
}
__device__ __forceinline__ float rsum32(float v){
  #pragma unroll
  for (int o=16;o;o>>=1) v += __shfl_xor_sync(0xffffffffu, v, o);
  return v;
}
__device__ __forceinline__ float rsum16(float v){
  #pragma unroll
  for (int o=8;o;o>>=1) v += __shfl_xor_sync(0xffffffffu, v, o);
  return v;
}
__device__ __forceinline__ float rmax16(float v){
  #pragma unroll
  for (int o=8;o;o>>=1) v = fmaxf(v, __shfl_xor_sync(0xffffffffu, v, o));
  return v;
}
__device__ __forceinline__ float sigm(float x){ return 1.f/(1.f+expf(-x)); }
__device__ __forceinline__ float splus(float x){ return fmaxf(x,0.f)+log1pf(expf(-fabsf(x))); }

struct Smem {
  float sciT[260][4];
  float sh1T[128][4];
  float sct2[128][4];
  float sc[4][16][132];
  float smix[4][16][16];
  float satt[4][128];
  float sbuf[16][4][128];
  float ssp[4][16], smaM[4][16], sal[4][16], sgs[4][16];
  float ssq[4][16], sms[4][16], smm[4][16];
  float sraw[4][4][16];
  float sred[4][4][3];
  float snv[4], srl[4], sval[4];
  int   sidx[4];
};

__global__ void __launch_bounds__(512,1) cfrm_kernel(
   const int* __restrict__ tokens, const float* __restrict__ emb,
   const float* __restrict__ ln_g, const float* __restrict__ ln_b,
   const float* __restrict__ w1, const float* __restrict__ b1,
   const float* __restrict__ w2, const float* __restrict__ b2,
   const float* __restrict__ gate_w, const float* __restrict__ gate_b,
   const float* __restrict__ assign_w, const float* __restrict__ assign_b,
   const float* __restrict__ nov_w, const float* __restrict__ nov_b,
   const float* __restrict__ relax_w, const float* __restrict__ relax_b,
   const float* __restrict__ cc_w, const float* __restrict__ cc_b,
   const float* __restrict__ cs_w, const float* __restrict__ cs_b,
   const float* __restrict__ md_w, const float* __restrict__ md_b,
   const float* __restrict__ att_w, const float* __restrict__ att_b,
   const float* __restrict__ cw1, const float* __restrict__ cb1,
   const float* __restrict__ cw2, const float* __restrict__ cb2,
   float* __restrict__ out)
{
  extern __shared__ __align__(128) char smem_raw[];
  Smem* S = (Smem*)smem_raw;

  const int tid  = threadIdx.x;
  const int g    = tid >> 7;
  const int ht   = tid & 127;
  const int lane = tid & 31;
  const int wg   = (tid >> 5) & 3;
  const int b    = blockIdx.x * 4 + g;

  const int j4  = tid & 31;
  const int isl = tid >> 5;

  for (int i = tid; i < 4*16*132; i += 512) ((float*)S->sc)[i] = 0.f;
  if (tid < 64){ ((float*)S->ssp)[tid] = 1.f; ((float*)S->smaM)[tid] = 0.f; }
  __syncthreads();

  for (int t = 0; t < 512; t++){
    const int tok = tokens[b*512 + t];
    const float valid = (tok != 0) ? 1.f : 0.f;
    if (ht == 0) S->sval[g] = valid;
    const float e = emb[tok*128 + ht];
    {
      float ps = rsum32(e);
      float pq = rsum32(e*e);
      if (lane == 0){ S->sred[g][wg][0] = ps; S->sred[g][wg][1] = pq; }
    }
    if (ht < 32){
      const bool ok = lane < 16;
      float sp = ok ? S->ssp[g][lane] : 0.f;
      float m  = ok ? S->smaM[g][lane] : 0.f;
      float score = ok ? m + logf(1.f/(sp+EPSF)+EPSF) : -3.4e38f;
      float mx = rmax16(score);
      float ex = ok ? expf(score - mx) : 0.f;
      float sm = rsum16(ex);
      float a  = ex / sm;
      if (ok) S->sal[g][lane] = a;
      float u   = rsum16(ok ? a*sp : 0.f);
      float ent = rsum16(ok ? -a*logf(fmaxf(a,1e-8f)) : 0.f);
      float mm2 = rmax16(ok ? m : -3.4e38f);
      float en  = mm2 + logf(rsum16(ok ? expf(m - mm2) : 0.f));
      if (lane == 0){ S->sciT[256][g] = u; S->sciT[258][g] = en; S->sciT[259][g] = ent; }
    }
    __syncthreads(); // S1
    {
      float mu = (S->sred[g][0][0]+S->sred[g][1][0]+S->sred[g][2][0]+S->sred[g][3][0]) * (1.f/128.f);
      float mq = (S->sred[g][0][1]+S->sred[g][1][1]+S->sred[g][2][1]+S->sred[g][3][1]) * (1.f/128.f);
      float var = mq - mu*mu;
      float te = (e - mu) * rsqrtf(var + 1e-5f) * ln_g[ht] + ln_b[ht];
      S->sciT[ht][g] = te;
      float core = 0.f;
      #pragma unroll
      for (int c = 0; c < 16; c++) core += S->sal[g][c] * S->sc[g][c][ht];
      S->sciT[128+ht][g] = core;
      float dv = 0.f;
      #pragma unroll
      for (int c = 0; c < 16; c++){ float dd = S->sc[g][c][ht] - core; dv += S->sal[g][c]*dd*dd; }
      dv = rsum32(dv);
      if (lane == 0) S->sred[g][wg][2] = dv;
    }
    __syncthreads(); // S2a
    if (ht == 0)
      S->sciT[257][g] = (S->sred[g][0][2]+S->sred[g][1][2]+S->sred[g][2][2]+S->sred[g][3][2]) * (1.f/128.f);
    __syncthreads(); // S2b

    // ---- w1 [260,128]: PF=2 pipelined ----
    {
      u64 aA[4] = {0,0,0,0}, aB[4] = {0,0,0,0};
      const int lo = isl * 16;
      ulonglong2 wb0 = *(const ulonglong2*)&w1[(lo+0)*128 + j4*4];
      ulonglong2 wb1 = *(const ulonglong2*)&w1[(lo+1)*128 + j4*4];
      #pragma unroll 2
      for (int r = 0; r < 16; r++){
        const int i = lo + r;
        ulonglong2 w = (r & 1) ? wb1 : wb0;
        if (r < 14){
          if (r & 1) wb1 = *(const ulonglong2*)&w1[(i+2)*128 + j4*4];
          else       wb0 = *(const ulonglong2*)&w1[(i+2)*128 + j4*4];
        }
        float4 x = *(const float4*)&S->sciT[i][0];
        u64 p0=pack2(x.x), p1=pack2(x.y), p2=pack2(x.z), p3=pack2(x.w);
        fma2(aA[0], p0, w.x); fma2(aB[0], p0, w.y);
        fma2(aA[1], p1, w.x); fma2(aB[1], p1, w.y);
        fma2(aA[2], p2, w.x); fma2(aB[2], p2, w.y);
        fma2(aA[3], p3, w.x); fma2(aB[3], p3, w.y);
      }
      if (isl < 4){
        const int i = 256 + isl;
        ulonglong2 w = *(const ulonglong2*)&w1[i*128 + j4*4];
        float4 x = *(const float4*)&S->sciT[i][0];
        u64 p0=pack2(x.x), p1=pack2(x.y), p2=pack2(x.z), p3=pack2(x.w);
        fma2(aA[0], p0, w.x); fma2(aB[0], p0, w.y);
        fma2(aA[1], p1, w.x); fma2(aB[1], p1, w.y);
        fma2(aA[2], p2, w.x); fma2(aB[2], p2, w.y);
        fma2(aA[3], p3, w.x); fma2(aB[3], p3, w.y);
      }
      #pragma unroll
      for (int b2 = 0; b2 < 4; b2++){
        float2 l = unpack2(aA[b2]), h2 = unpack2(aB[b2]);
        *(float4*)&S->sbuf[isl][b2][j4*4] = make_float4(l.x, l.y, h2.x, h2.y);
      }
    }
    __syncthreads(); // S3
    {
      float s = b1[ht];
      #pragma unroll
      for (int k = 0; k < 16; k++) s += S->sbuf[k][g][ht];
      S->sh1T[ht][g] = tanhf(s);
    }
    __syncthreads(); // S4

    // ---- w2 [128,128]: PF=2 pipelined ----
    {
      u64 aA[4] = {0,0,0,0}, aB[4] = {0,0,0,0};
      const int lo = isl * 8;
      ulonglong2 wb0 = *(const ulonglong2*)&w2[(lo+0)*128 + j4*4];
      ulonglong2 wb1 = *(const ulonglong2*)&w2[(lo+1)*128 + j4*4];
      #pragma unroll 2
      for (int r = 0; r < 8; r++){
        const int i = lo + r;
        ulonglong2 w = (r & 1) ? wb1 : wb0;
        if (r < 6){
          if (r & 1) wb1 = *(const ulonglong2*)&w2[(i+2)*128 + j4*4];
          else       wb0 = *(const ulonglong2*)&w2[(i+2)*128 + j4*4];
        }
        float4 x = *(const float4*)&S->sh1T[i][0];
        u64 p0=pack2(x.x), p1=pack2(x.y), p2=pack2(x.z), p3=pack2(x.w);
        fma2(aA[0], p0, w.x); fma2(aB[0], p0, w.y);
        fma2(aA[1], p1, w.x); fma2(aB[1], p1, w.y);
        fma2(aA[2], p2, w.x); fma2(aB[2], p2, w.y);
        fma2(aA[3], p3, w.x); fma2(aB[3], p3, w.y);
      }
      #pragma unroll
      for (int b2 = 0; b2 < 4; b2++){
        float2 l = unpack2(aA[b2]), h2 = unpack2(aB[b2]);
        *(float4*)&S->sbuf[isl][b2][j4*4] = make_float4(l.x, l.y, h2.x, h2.y);
      }
    }
    __syncthreads(); // S5
    {
      float s = b2[ht];
      #pragma unroll
      for (int k = 0; k < 16; k++) s += S->sbuf[k][g][ht];
      S->sct2[ht][g] = tanhf(s);
    }
    __syncthreads(); // S6

    // ---- cc_w [128,2048]: PF=2 pipelined, one LDG.128 feeds 4 batches ----
    u64 A0[2] = {0,0}, A1[2] = {0,0}, A2[2] = {0,0}, A3[2] = {0,0};
    {
      const ulonglong2* W = (const ulonglong2*)cc_w;
      ulonglong2 wb0 = W[tid];
      ulonglong2 wb1 = W[512 + tid];
      #pragma unroll 2
      for (int i = 0; i < 128; i++){
        ulonglong2 wv = (i & 1) ? wb1 : wb0;
        if (i < 126){
          if (i & 1) wb1 = W[(i+2)*512 + tid];
          else       wb0 = W[(i+2)*512 + tid];
        }
        float4 ct = *(const float4*)&S->sct2[i][0];
        u64 p0 = pack2(ct.x), p1 = pack2(ct.y), p2 = pack2(ct.z), p3 = pack2(ct.w);
        fma2(A0[0], p0, wv.x); fma2(A0[1], p0, wv.y);
        fma2(A1[0], p1, wv.x); fma2(A1[1], p1, wv.y);
        fma2(A2[0], p2, wv.x); fma2(A2[1], p2, wv.y);
        fma2(A3[0], p3, wv.x); fma2(A3[1], p3, wv.y);
      }
    }

    // ---- att_w [128,128]: PF=2 pipelined ----
    {
      u64 aA[4] = {0,0,0,0}, aB[4] = {0,0,0,0};
      const int lo = isl * 8;
      ulonglong2 wb0 = *(const ulonglong2*)&att_w[(lo+0)*128 + j4*4];
      ulonglong2 wb1 = *(const ulonglong2*)&att_w[(lo+1)*128 + j4*4];
      #pragma unroll 2
      for (int r = 0; r < 8; r++){
        const int i = lo + r;
        ulonglong2 w = (r & 1) ? wb1 : wb0;
        if (r < 6){
          if (r & 1) wb1 = *(const ulonglong2*)&att_w[(i+2)*128 + j4*4];
          else       wb0 = *(const ulonglong2*)&att_w[(i+2)*128 + j4*4];
        }
        float4 x = *(const float4*)&S->sct2[i][0];
        u64 p0=pack2(x.x), p1=pack2(x.y), p2=pack2(x.z), p3=pack2(x.w);
        fma2(aA[0], p0, w.x); fma2(aB[0], p0, w.y);
        fma2(aA[1], p1, w.x); fma2(aB[1], p1, w.y);
        fma2(aA[2], p2, w.x); fma2(aB[2], p2, w.y);
        fma2(aA[3], p3, w.x); fma2(aB[3], p3, w.y);
      }
      #pragma unroll
      for (int b2 = 0; b2 < 4; b2++){
        float2 l = unpack2(aA[b2]), h2 = unpack2(aB[b2]);
        *(float4*)&S->sbuf[isl][b2][j4*4] = make_float4(l.x, l.y, h2.x, h2.y);
      }
    }

    // ---- small heads + nov/relax ----
    if (ht < 64){
      const int head = ht >> 4;
      const int c = ht & 15;
      const float* W  = (head==0)? gate_w : (head==1)? assign_w : (head==2)? cs_w : md_w;
      const float* Bp = (head==0)? gate_b : (head==1)? assign_b : (head==2)? cs_b : md_b;
      float s = Bp[c];
      #pragma unroll 8
      for (int i = 0; i < 128; i++) s += S->sct2[i][g] * W[i*16 + c];
      S->sraw[g][head][c] = s;
    } else if (ht < 96){
      float s = 0.f;
      #pragma unroll
      for (int k = 0; k < 4; k++){ int i = (ht-64) + k*32; s += S->sct2[i][g] * nov_w[i]; }
      s = rsum32(s);
      if (lane == 0) S->snv[g] = sigm(s + nov_b[0]) * S->sval[g];
    } else {
      float s = 0.f;
      #pragma unroll
      for (int k = 0; k < 4; k++){ int i = (ht-96) + k*32; s += S->sct2[i][g] * relax_w[i]; }
      s = rsum32(s);
      if (lane == 0) S->srl[g] = sigm(s + relax_b[0]) * S->sval[g];
    }
    __syncthreads(); // S7
    {
      float s = att_b[ht];
      #pragma unroll
      for (int k = 0; k < 16; k++) s += S->sbuf[k][g][ht];
      S->satt[g][ht] = s;
    }
    if (ht < 32){
      const bool ok = lane < 16;
      float graw = ok ? S->sraw[g][0][lane] : 0.f;
      float araw = ok ? S->sraw[g][1][lane] : -3.4e38f;
      float mx = rmax16(araw);
      float ex = ok ? expf(araw - mx) : 0.f;
      float sm = rsum16(ex);
      if (ok){
        float assign = ex / sm;
        float gate = sigm(graw) * S->sval[g];
        float ss = gate * assign;
        S->sgs[g][lane] = ss;
        float cs = splus(S->sraw[g][2][lane]) + EPSF;
        float md = tanhf(S->sraw[g][3][lane]);
        float sp = S->ssp[g][lane]; sp += ss*(cs - sp); S->ssp[g][lane] = sp;
        float m  = S->smaM[g][lane]; m += ss*md;        S->smaM[g][lane] = m;
      }
    }
    __syncthreads(); // S8

    // ---- center update (explicitly unrolled, no pointer array) ----
    {
      const int ccC = tid >> 5, ccH = tid & 31;
      float4 bv = *(const float4*)&cc_b[ccC*128 + ccH*4];
      float4 at0 = *(const float4*)&S->satt[0][ccH*4];
      float4 at1 = *(const float4*)&S->satt[1][ccH*4];
      float4 at2 = *(const float4*)&S->satt[2][ccH*4];
      float4 at3 = *(const float4*)&S->satt[3][ccH*4];
#define CUPD(GG, AX, AT) do{ \
      float2 l  = unpack2(AX[0]); \
      float2 hh = unpack2(AX[1]); \
      float4 cand = make_float4(l.x+bv.x, l.y+bv.y, hh.x+bv.z, hh.y+bv.w); \
      float ssv = S->sgs[GG][ccC]; \
      float nv  = 0.1f * S->snv[GG]; \
      float4 v  = *(float4*)&S->sc[GG][ccC][ccH*4]; \
      v.x += ssv*(cand.x - v.x); v.x += nv*(AT.x - v.x); \
      v.y += ssv*(cand.y - v.y); v.y += nv*(AT.y - v.y); \
      v.z += ssv*(cand.z - v.z); v.z += nv*(AT.z - v.z); \
      v.w += ssv*(cand.w - v.w); v.w += nv*(AT.w - v.w); \
      *(float4*)&S->sc[GG][ccC][ccH*4] = v; }while(0)
      CUPD(0, A0, at0);
      CUPD(1, A1, at1);
      CUPD(2, A2, at2);
      CUPD(3, A3, at3);
#undef CUPD
    }
    __syncthreads(); // S9

    // ---- Gram ----
    {
      #pragma unroll
      for (int pp = 0; pp < 2; pp++){
        int p = ht + pp*128;
        int ii = p >> 4, jj = p & 15;
        const float4* Aa = (const float4*)S->sc[g][ii];
        const float4* Bv = (const float4*)S->sc[g][jj];
        float d0=0.f, d1=0.f, d2s=0.f, d3=0.f;
        #pragma unroll 8
        for (int k = 0; k < 32; k++){
          float4 a4 = Aa[k], b4 = Bv[k];
          d0 += a4.x*b4.x; d1 += a4.y*b4.y; d2s += a4.z*b4.z; d3 += a4.w*b4.w;
        }
        float dot = (d0+d1) + (d2s+d3);
        S->smix[g][ii][jj] = dot;
        if (ii == jj) S->ssq[g][ii] = dot;
      }
    }
    __syncthreads(); // S10
    {
      #pragma unroll
      for (int pass = 0; pass < 2; pass++){
        int row = pass*8 + wg*2 + (lane >> 4);
        int jj  = lane & 15;
        float Gij = S->smix[g][row][jj];
        float d2v = fmaxf(S->ssq[g][row] + S->ssq[g][jj] - 2.f*Gij, 0.f);
        float comp = -d2v / (S->ssp[g][row] + S->ssp[g][jj] + EPSF) + S->smaM[g][jj];
        float mx = rmax16(comp);
        float ex = expf(comp - mx);
        float sm = rsum16(ex);
        float mix = ex / sm;
        S->smix[g][row][jj] = mix;
        float msp = rsum16(mix * S->ssp[g][jj]);
        float mms = rsum16(mix * S->smaM[g][jj]);
        if ((lane & 15) == 0){ S->sms[g][row] = msp; S->smm[g][row] = mms; }
      }
    }
    __syncthreads(); // S11
    {
      float rl = S->srl[g];
      float cr[16];
      #pragma unroll
      for (int c = 0; c < 16; c++) cr[c] = S->sc[g][c][ht];
      #pragma unroll
      for (int i = 0; i < 16; i++){
        const float4* mr = (const float4*)S->smix[g][i];
        float4 m0 = mr[0], m1 = mr[1], m2v = mr[2], m3 = mr[3];
        float mc = m0.x*cr[0]+m0.y*cr[1]+m0.z*cr[2]+m0.w*cr[3]
                 + m1.x*cr[4]+m1.y*cr[5]+m1.z*cr[6]+m1.w*cr[7]
                 + m2v.x*cr[8]+m2v.y*cr[9]+m2v.z*cr[10]+m2v.w*cr[11]
                 + m3.x*cr[12]+m3.y*cr[13]+m3.z*cr[14]+m3.w*cr[15];
        S->sc[g][i][ht] = (1.f-rl)*cr[i] + rl*mc;
      }
      if (ht < 32){
        const bool ok = lane < 16;
        float rl2 = S->srl[g];
        float sp = ok ? S->ssp[g][lane] : 1.f;
        float m  = ok ? S->smaM[g][lane] : 0.f;
        float sp2 = (1.f-rl2)*sp + rl2*(ok ? S->sms[g][lane] : 0.f);
        float m2  = (1.f-rl2)*m  + rl2*(ok ? S->smm[g][lane] : 0.f);
        float score = ok ? m2 + logf(1.f/(sp2+EPSF)+EPSF) : -3.4e38f;
        float mx = rmax16(score);
        float ex = ok ? expf(score - mx) : 0.f;
        float sm = rsum16(ex);
        float ca = ex / sm;
        if (ok){ S->ssp[g][lane] = sp2*(1.f - 0.05f*ca*S->sval[g]) + EPSF; S->smaM[g][lane] = m2; }
      }
    }
    __syncthreads(); // S12
  }

  // ---- epilogue ----
  if (ht < 32){
    const bool ok = lane < 16;
    float sp = ok ? S->ssp[g][lane] : 0.f;
    float m  = ok ? S->smaM[g][lane] : 0.f;
    float score = ok ? m + logf(1.f/(sp+EPSF)+EPSF) : -3.4e38f;
    float mx = rmax16(score);
    float ex = ok ? expf(score - mx) : 0.f;
    float sm = rsum16(ex);
    float a  = ex / sm;
    if (ok) S->sal[g][lane] = a;
    float u   = rsum16(ok ? a*sp : 0.f);
    float ent = rsum16(ok ? -a*logf(fmaxf(a,1e-8f)) : 0.f);
    float mm2 = rmax16(ok ? m : -3.4e38f);
    float en  = mm2 + logf(rsum16(ok ? expf(m - mm2) : 0.f));
    float bv = ok ? a : -3.4e38f;
    int   bi = ok ? lane : 99;
    #pragma unroll
    for (int o = 8; o; o >>= 1){
      float ov = __shfl_xor_sync(0xffffffffu, bv, o);
      int   oi = __shfl_xor_sync(0xffffffffu, bi, o);
      if (ov > bv || (ov == bv && oi < bi)){ bv = ov; bi = oi; }
    }
    if (lane == 0){
      S->sciT[256][g] = u; S->sciT[258][g] = en; S->sciT[259][g] = ent; S->sidx[g] = bi;
    }
  }
  __syncthreads();
  {
    float core = 0.f;
    #pragma unroll
    for (int c = 0; c < 16; c++) core += S->sal[g][c] * S->sc[g][c][ht];
    float dv = 0.f;
    #pragma unroll
    for (int c = 0; c < 16; c++){ float dd = S->sc[g][c][ht] - core; dv += S->sal[g][c]*dd*dd; }
    dv = rsum32(dv);
    if (lane == 0) S->sred[g][wg][2] = dv;
    float strong = S->sc[g][S->sidx[g]][ht];
    S->sciT[ht][g] = core;
    S->sciT[128+ht][g] = strong;
  }
  __syncthreads();
  if (ht == 0)
    S->sciT[257][g] = (S->sred[g][0][2]+S->sred[g][1][2]+S->sred[g][2][2]+S->sred[g][3][2]) * (1.f/128.f);
  __syncthreads();
  {
    u64 aA[4] = {0,0,0,0}, aB[4] = {0,0,0,0};
    const int lo = isl * 16;
    #pragma unroll 8
    for (int i = lo; i < lo + 16; i++){
      ulonglong2 w = *(const ulonglong2*)&cw1[i*128 + j4*4];
      float4 x = *(const float4*)&S->sciT[i][0];
      u64 p0=pack2(x.x), p1=pack2(x.y), p2=pack2(x.z), p3=pack2(x.w);
      fma2(aA[0], p0, w.x); fma2(aB[0], p0, w.y);
      fma2(aA[1], p1, w.x); fma2(aB[1], p1, w.y);
      fma2(aA[2], p2, w.x); fma2(aB[2], p2, w.y);
      fma2(aA[3], p3, w.x); fma2(aB[3], p3, w.y);
    }
    if (isl < 4){
      const int i = 256 + isl;
      ulonglong2 w = *(const ulonglong2*)&cw1[i*128 + j4*4];
      float4 x = *(const float4*)&S->sciT[i][0];
      u64 p0=pack2(x.x), p1=pack2(x.y), p2=pack2(x.z), p3=pack2(x.w);
      fma2(aA[0], p0, w.x); fma2(aB[0], p0, w.y);
      fma2(aA[1], p1, w.x); fma2(aB[1], p1, w.y);
      fma2(aA[2], p2, w.x); fma2(aB[2], p2, w.y);
      fma2(aA[3], p3, w.x); fma2(aB[3], p3, w.y);
    }
    #pragma unroll
    for (int b2 = 0; b2 < 4; b2++){
      float2 l = unpack2(aA[b2]), h2 = unpack2(aB[b2]);
      *(float4*)&S->sbuf[isl][b2][j4*4] = make_float4(l.x, l.y, h2.x, h2.y);
    }
  }
  __syncthreads();
  {
    float s = cb1[ht];
    #pragma unroll
    for (int k = 0; k < 16; k++) s += S->sbuf[k][g][ht];
    S->sh1T[ht][g] = 0.5f * s * (1.f + erff(s * 0.70710678118654752440f));
  }
  __syncthreads();
  if (ht < 8){
    float s = cb2[ht];
    #pragma unroll 4
    for (int i = 0; i < 128; i++) s += S->sh1T[i][g] * cw2[i*8 + ht];
    out[b*8 + ht] = s;
  }
}

extern "C" void kernel_launch(void* const* d_in, const int* in_sizes, int n_in,
                              void* d_out, int out_size){
  (void)in_sizes; (void)n_in; (void)out_size;
  cudaFuncSetAttribute(cfrm_kernel, cudaFuncAttributeMaxDynamicSharedMemorySize, (int)sizeof(Smem));
  cfrm_kernel<<<32, 512, sizeof(Smem)>>>(
    (const int*)  d_in[0],  (const float*)d_in[1],  (const float*)d_in[2],  (const float*)d_in[3],
    (const float*)d_in[4],  (const float*)d_in[5],  (const float*)d_in[6],  (const float*)d_in[7],
    (const float*)d_in[8],  (const float*)d_in[9],  (const float*)d_in[10], (const float*)d_in[11],
    (const float*)d_in[12], (const float*)d_in[13], (const float*)d_in[14], (const float*)d_in[15],
    (const float*)d_in[16], (const float*)d_in[17], (const float*)d_in[18], (const float*)d_in[19],
    (const float*)d_in[20], (const float*)d_in[21], (const float*)d_in[22], (const float*)d_in[23],
    (const float*)d_in[24], (const float*)d_in[25], (const float*)d_in[26], (const float*)d_in[27],
    (float*)d_out);
}

// round 10
// speedup vs baseline: 1.3774x; 1.3774x over previous
#include <cuda_runtime.h>
#include <math.h>

#define EPSF 1e-4f
typedef unsigned long long u64;

__device__ __forceinline__ u64 pack2(float x){
  u64 r; unsigned xi = __float_as_uint(x);
  asm("mov.b64 %0, {%1, %1};" : "=l"(r) : "r"(xi));
  return r;
}
__device__ __forceinline__ void fma2(u64 &acc, u64 a, u64 b){
  asm("fma.rn.f32x2 %0, %1, %2, %0;" : "+l"(acc) : "l"(a), "l"(b));
}
__device__ __forceinline__ float2 unpack2(u64 v){
  unsigned lo, hi;
  asm("mov.b64 {%0, %1}, %2;" : "=r"(lo), "=r"(hi) : "l"(v));
  return make_float2(__uint_as_float(lo), __uint_as_float(hi));
}
__device__ __forceinline__ float rsum32(float v){
  #pragma unroll
  for (int o=16;o;o>>=1) v += __shfl_xor_sync(0xffffffffu, v, o);
  return v;
}
__device__ __forceinline__ float rsum16(float v){
  #pragma unroll
  for (int o=8;o;o>>=1) v += __shfl_xor_sync(0xffffffffu, v, o);
  return v;
}
__device__ __forceinline__ float rmax16(float v){
  #pragma unroll
  for (int o=8;o;o>>=1) v = fmaxf(v, __shfl_xor_sync(0xffffffffu, v, o));
  return v;
}
__device__ __forceinline__ float sigm(float x){ return 1.f/(1.f+expf(-x)); }
__device__ __forceinline__ float splus(float x){ return fmaxf(x,0.f)+log1pf(expf(-fabsf(x))); }

struct Smem {
  float sciT[260][4];
  float sh1T[128][4];
  float sct2[128][4];
  float sc[4][16][132];
  float smix[4][16][16];
  float satt[4][128];
  float sbuf[16][4][128];
  float ssp[4][16], smaM[4][16], sal[4][16], sgs[4][16];
  float ssq[4][16], sms[4][16], smm[4][16];
  float sraw[4][4][16];
  float sred[4][4][3];
  float snv[4], srl[4], sval[4];
  int   sidx[4];
};

__global__ void __launch_bounds__(512,1) cfrm_kernel(
   const int* __restrict__ tokens, const float* __restrict__ emb,
   const float* __restrict__ ln_g, const float* __restrict__ ln_b,
   const float* __restrict__ w1, const float* __restrict__ b1,
   const float* __restrict__ w2, const float* __restrict__ b2,
   const float* __restrict__ gate_w, const float* __restrict__ gate_b,
   const float* __restrict__ assign_w, const float* __restrict__ assign_b,
   const float* __restrict__ nov_w, const float* __restrict__ nov_b,
   const float* __restrict__ relax_w, const float* __restrict__ relax_b,
   const float* __restrict__ cc_w, const float* __restrict__ cc_b,
   const float* __restrict__ cs_w, const float* __restrict__ cs_b,
   const float* __restrict__ md_w, const float* __restrict__ md_b,
   const float* __restrict__ att_w, const float* __restrict__ att_b,
   const float* __restrict__ cw1, const float* __restrict__ cb1,
   const float* __restrict__ cw2, const float* __restrict__ cb2,
   float* __restrict__ out)
{
  extern __shared__ __align__(128) char smem_raw[];
  Smem* S = (Smem*)smem_raw;

  const int tid  = threadIdx.x;
  const int g    = tid >> 7;
  const int ht   = tid & 127;
  const int lane = tid & 31;
  const int wg   = (tid >> 5) & 3;
  const int b    = blockIdx.x * 4 + g;

  const int j4  = tid & 31;
  const int isl = tid >> 5;

  for (int i = tid; i < 4*16*132; i += 512) ((float*)S->sc)[i] = 0.f;
  if (tid < 64){ ((float*)S->ssp)[tid] = 1.f; ((float*)S->smaM)[tid] = 0.f; }
  __syncthreads();

  for (int t = 0; t < 512; t++){
    const int tok = tokens[b*512 + t];
    const float valid = (tok != 0) ? 1.f : 0.f;
    if (ht == 0) S->sval[g] = valid;
    const float e = emb[tok*128 + ht];
    {
      float ps = rsum32(e);
      float pq = rsum32(e*e);
      if (lane == 0){ S->sred[g][wg][0] = ps; S->sred[g][wg][1] = pq; }
    }
    if (ht < 32){
      const bool ok = lane < 16;
      float sp = ok ? S->ssp[g][lane] : 0.f;
      float m  = ok ? S->smaM[g][lane] : 0.f;
      float score = ok ? m + logf(1.f/(sp+EPSF)+EPSF) : -3.4e38f;
      float mx = rmax16(score);
      float ex = ok ? expf(score - mx) : 0.f;
      float sm = rsum16(ex);
      float a  = ex / sm;
      if (ok) S->sal[g][lane] = a;
      float u   = rsum16(ok ? a*sp : 0.f);
      float ent = rsum16(ok ? -a*logf(fmaxf(a,1e-8f)) : 0.f);
      float mm2 = rmax16(ok ? m : -3.4e38f);
      float en  = mm2 + logf(rsum16(ok ? expf(m - mm2) : 0.f));
      if (lane == 0){ S->sciT[256][g] = u; S->sciT[258][g] = en; S->sciT[259][g] = ent; }
    }
    __syncthreads(); // S1
    {
      float mu = (S->sred[g][0][0]+S->sred[g][1][0]+S->sred[g][2][0]+S->sred[g][3][0]) * (1.f/128.f);
      float mq = (S->sred[g][0][1]+S->sred[g][1][1]+S->sred[g][2][1]+S->sred[g][3][1]) * (1.f/128.f);
      float var = mq - mu*mu;
      float te = (e - mu) * rsqrtf(var + 1e-5f) * ln_g[ht] + ln_b[ht];
      S->sciT[ht][g] = te;
      float core = 0.f;
      #pragma unroll
      for (int c = 0; c < 16; c++) core += S->sal[g][c] * S->sc[g][c][ht];
      S->sciT[128+ht][g] = core;
      float dv = 0.f;
      #pragma unroll
      for (int c = 0; c < 16; c++){ float dd = S->sc[g][c][ht] - core; dv += S->sal[g][c]*dd*dd; }
      dv = rsum32(dv);
      if (lane == 0) S->sred[g][wg][2] = dv;
    }
    __syncthreads(); // S2a
    if (ht == 0)
      S->sciT[257][g] = (S->sred[g][0][2]+S->sred[g][1][2]+S->sred[g][2][2]+S->sred[g][3][2]) * (1.f/128.f);
    __syncthreads(); // S2b

    // ---- w1 [260,128]: 16 slices, fully unrolled 16+tail ----
    {
      u64 aA[4] = {0,0,0,0}, aB[4] = {0,0,0,0};
      const int lo = isl * 16;
      #pragma unroll
      for (int r = 0; r < 16; r++){
        const int i = lo + r;
        ulonglong2 w = *(const ulonglong2*)&w1[i*128 + j4*4];
        float4 x = *(const float4*)&S->sciT[i][0];
        u64 p0=pack2(x.x), p1=pack2(x.y), p2=pack2(x.z), p3=pack2(x.w);
        fma2(aA[0], p0, w.x); fma2(aB[0], p0, w.y);
        fma2(aA[1], p1, w.x); fma2(aB[1], p1, w.y);
        fma2(aA[2], p2, w.x); fma2(aB[2], p2, w.y);
        fma2(aA[3], p3, w.x); fma2(aB[3], p3, w.y);
      }
      if (isl < 4){
        const int i = 256 + isl;
        ulonglong2 w = *(const ulonglong2*)&w1[i*128 + j4*4];
        float4 x = *(const float4*)&S->sciT[i][0];
        u64 p0=pack2(x.x), p1=pack2(x.y), p2=pack2(x.z), p3=pack2(x.w);
        fma2(aA[0], p0, w.x); fma2(aB[0], p0, w.y);
        fma2(aA[1], p1, w.x); fma2(aB[1], p1, w.y);
        fma2(aA[2], p2, w.x); fma2(aB[2], p2, w.y);
        fma2(aA[3], p3, w.x); fma2(aB[3], p3, w.y);
      }
      #pragma unroll
      for (int b2 = 0; b2 < 4; b2++){
        float2 l = unpack2(aA[b2]), h2 = unpack2(aB[b2]);
        *(float4*)&S->sbuf[isl][b2][j4*4] = make_float4(l.x, l.y, h2.x, h2.y);
      }
    }
    __syncthreads(); // S3
    {
      float s = b1[ht];
      #pragma unroll
      for (int k = 0; k < 16; k++) s += S->sbuf[k][g][ht];
      S->sh1T[ht][g] = tanhf(s);
    }
    __syncthreads(); // S4

    // ---- w2 [128,128]: full unroll 8 ----
    {
      u64 aA[4] = {0,0,0,0}, aB[4] = {0,0,0,0};
      const int lo = isl * 8;
      #pragma unroll
      for (int r = 0; r < 8; r++){
        const int i = lo + r;
        ulonglong2 w = *(const ulonglong2*)&w2[i*128 + j4*4];
        float4 x = *(const float4*)&S->sh1T[i][0];
        u64 p0=pack2(x.x), p1=pack2(x.y), p2=pack2(x.z), p3=pack2(x.w);
        fma2(aA[0], p0, w.x); fma2(aB[0], p0, w.y);
        fma2(aA[1], p1, w.x); fma2(aB[1], p1, w.y);
        fma2(aA[2], p2, w.x); fma2(aB[2], p2, w.y);
        fma2(aA[3], p3, w.x); fma2(aB[3], p3, w.y);
      }
      #pragma unroll
      for (int b2 = 0; b2 < 4; b2++){
        float2 l = unpack2(aA[b2]), h2 = unpack2(aB[b2]);
        *(float4*)&S->sbuf[isl][b2][j4*4] = make_float4(l.x, l.y, h2.x, h2.y);
      }
    }
    __syncthreads(); // S5
    {
      float s = b2[ht];
      #pragma unroll
      for (int k = 0; k < 16; k++) s += S->sbuf[k][g][ht];
      S->sct2[ht][g] = tanhf(s);
    }
    __syncthreads(); // S6

    // ---- cc_w [128,2048]: unroll 16, straight-line loads ----
    u64 A0[2] = {0,0}, A1[2] = {0,0}, A2[2] = {0,0}, A3[2] = {0,0};
    {
      const ulonglong2* W = (const ulonglong2*)cc_w;
      #pragma unroll 16
      for (int i = 0; i < 128; i++){
        ulonglong2 wv = W[i*512 + tid];
        float4 ct = *(const float4*)&S->sct2[i][0];
        u64 p0 = pack2(ct.x), p1 = pack2(ct.y), p2 = pack2(ct.z), p3 = pack2(ct.w);
        fma2(A0[0], p0, wv.x); fma2(A0[1], p0, wv.y);
        fma2(A1[0], p1, wv.x); fma2(A1[1], p1, wv.y);
        fma2(A2[0], p2, wv.x); fma2(A2[1], p2, wv.y);
        fma2(A3[0], p3, wv.x); fma2(A3[1], p3, wv.y);
      }
    }

    // ---- att_w [128,128]: full unroll 8 ----
    {
      u64 aA[4] = {0,0,0,0}, aB[4] = {0,0,0,0};
      const int lo = isl * 8;
      #pragma unroll
      for (int r = 0; r < 8; r++){
        const int i = lo + r;
        ulonglong2 w = *(const ulonglong2*)&att_w[i*128 + j4*4];
        float4 x = *(const float4*)&S->sct2[i][0];
        u64 p0=pack2(x.x), p1=pack2(x.y), p2=pack2(x.z), p3=pack2(x.w);
        fma2(aA[0], p0, w.x); fma2(aB[0], p0, w.y);
        fma2(aA[1], p1, w.x); fma2(aB[1], p1, w.y);
        fma2(aA[2], p2, w.x); fma2(aB[2], p2, w.y);
        fma2(aA[3], p3, w.x); fma2(aB[3], p3, w.y);
      }
      #pragma unroll
      for (int b2 = 0; b2 < 4; b2++){
        float2 l = unpack2(aA[b2]), h2 = unpack2(aB[b2]);
        *(float4*)&S->sbuf[isl][b2][j4*4] = make_float4(l.x, l.y, h2.x, h2.y);
      }
    }

    // ---- small heads + nov/relax ----
    if (ht < 64){
      const int head = ht >> 4;
      const int c = ht & 15;
      const float* W  = (head==0)? gate_w : (head==1)? assign_w : (head==2)? cs_w : md_w;
      const float* Bp = (head==0)? gate_b : (head==1)? assign_b : (head==2)? cs_b : md_b;
      float s = Bp[c];
      #pragma unroll 8
      for (int i = 0; i < 128; i++) s += S->sct2[i][g] * W[i*16 + c];
      S->sraw[g][head][c] = s;
    } else if (ht < 96){
      float s = 0.f;
      #pragma unroll
      for (int k = 0; k < 4; k++){ int i = (ht-64) + k*32; s += S->sct2[i][g] * nov_w[i]; }
      s = rsum32(s);
      if (lane == 0) S->snv[g] = sigm(s + nov_b[0]) * S->sval[g];
    } else {
      float s = 0.f;
      #pragma unroll
      for (int k = 0; k < 4; k++){ int i = (ht-96) + k*32; s += S->sct2[i][g] * relax_w[i]; }
      s = rsum32(s);
      if (lane == 0) S->srl[g] = sigm(s + relax_b[0]) * S->sval[g];
    }
    __syncthreads(); // S7
    {
      float s = att_b[ht];
      #pragma unroll
      for (int k = 0; k < 16; k++) s += S->sbuf[k][g][ht];
      S->satt[g][ht] = s;
    }
    if (ht < 32){
      const bool ok = lane < 16;
      float graw = ok ? S->sraw[g][0][lane] : 0.f;
      float araw = ok ? S->sraw[g][1][lane] : -3.4e38f;
      float mx = rmax16(araw);
      float ex = ok ? expf(araw - mx) : 0.f;
      float sm = rsum16(ex);
      if (ok){
        float assign = ex / sm;
        float gate = sigm(graw) * S->sval[g];
        float ss = gate * assign;
        S->sgs[g][lane] = ss;
        float cs = splus(S->sraw[g][2][lane]) + EPSF;
        float md = tanhf(S->sraw[g][3][lane]);
        float sp = S->ssp[g][lane]; sp += ss*(cs - sp); S->ssp[g][lane] = sp;
        float m  = S->smaM[g][lane]; m += ss*md;        S->smaM[g][lane] = m;
      }
    }
    __syncthreads(); // S8

    // ---- center update ----
    {
      const int ccC = tid >> 5, ccH = tid & 31;
      float4 bv = *(const float4*)&cc_b[ccC*128 + ccH*4];
      float4 at0 = *(const float4*)&S->satt[0][ccH*4];
      float4 at1 = *(const float4*)&S->satt[1][ccH*4];
      float4 at2 = *(const float4*)&S->satt[2][ccH*4];
      float4 at3 = *(const float4*)&S->satt[3][ccH*4];
#define CUPD(GG, AX, AT) do{ \
      float2 l  = unpack2(AX[0]); \
      float2 hh = unpack2(AX[1]); \
      float4 cand = make_float4(l.x+bv.x, l.y+bv.y, hh.x+bv.z, hh.y+bv.w); \
      float ssv = S->sgs[GG][ccC]; \
      float nv  = 0.1f * S->snv[GG]; \
      float4 v  = *(float4*)&S->sc[GG][ccC][ccH*4]; \
      v.x += ssv*(cand.x - v.x); v.x += nv*(AT.x - v.x); \
      v.y += ssv*(cand.y - v.y); v.y += nv*(AT.y - v.y); \
      v.z += ssv*(cand.z - v.z); v.z += nv*(AT.z - v.z); \
      v.w += ssv*(cand.w - v.w); v.w += nv*(AT.w - v.w); \
      *(float4*)&S->sc[GG][ccC][ccH*4] = v; }while(0)
      CUPD(0, A0, at0);
      CUPD(1, A1, at1);
      CUPD(2, A2, at2);
      CUPD(3, A3, at3);
#undef CUPD
    }
    __syncthreads(); // S9

    // ---- Gram ----
    {
      #pragma unroll
      for (int pp = 0; pp < 2; pp++){
        int p = ht + pp*128;
        int ii = p >> 4, jj = p & 15;
        const float4* Aa = (const float4*)S->sc[g][ii];
        const float4* Bv = (const float4*)S->sc[g][jj];
        float d0=0.f, d1=0.f, d2s=0.f, d3=0.f;
        #pragma unroll 8
        for (int k = 0; k < 32; k++){
          float4 a4 = Aa[k], b4 = Bv[k];
          d0 += a4.x*b4.x; d1 += a4.y*b4.y; d2s += a4.z*b4.z; d3 += a4.w*b4.w;
        }
        float dot = (d0+d1) + (d2s+d3);
        S->smix[g][ii][jj] = dot;
        if (ii == jj) S->ssq[g][ii] = dot;
      }
    }
    __syncthreads(); // S10
    {
      #pragma unroll
      for (int pass = 0; pass < 2; pass++){
        int row = pass*8 + wg*2 + (lane >> 4);
        int jj  = lane & 15;
        float Gij = S->smix[g][row][jj];
        float d2v = fmaxf(S->ssq[g][row] + S->ssq[g][jj] - 2.f*Gij, 0.f);
        float comp = -d2v / (S->ssp[g][row] + S->ssp[g][jj] + EPSF) + S->smaM[g][jj];
        float mx = rmax16(comp);
        float ex = expf(comp - mx);
        float sm = rsum16(ex);
        float mix = ex / sm;
        S->smix[g][row][jj] = mix;
        float msp = rsum16(mix * S->ssp[g][jj]);
        float mms = rsum16(mix * S->smaM[g][jj]);
        if ((lane & 15) == 0){ S->sms[g][row] = msp; S->smm[g][row] = mms; }
      }
    }
    __syncthreads(); // S11
    {
      float rl = S->srl[g];
      float cr[16];
      #pragma unroll
      for (int c = 0; c < 16; c++) cr[c] = S->sc[g][c][ht];
      #pragma unroll
      for (int i = 0; i < 16; i++){
        const float4* mr = (const float4*)S->smix[g][i];
        float4 m0 = mr[0], m1 = mr[1], m2v = mr[2], m3 = mr[3];
        float mc = m0.x*cr[0]+m0.y*cr[1]+m0.z*cr[2]+m0.w*cr[3]
                 + m1.x*cr[4]+m1.y*cr[5]+m1.z*cr[6]+m1.w*cr[7]
                 + m2v.x*cr[8]+m2v.y*cr[9]+m2v.z*cr[10]+m2v.w*cr[11]
                 + m3.x*cr[12]+m3.y*cr[13]+m3.z*cr[14]+m3.w*cr[15];
        S->sc[g][i][ht] = (1.f-rl)*cr[i] + rl*mc;
      }
      if (ht < 32){
        const bool ok = lane < 16;
        float rl2 = S->srl[g];
        float sp = ok ? S->ssp[g][lane] : 1.f;
        float m  = ok ? S->smaM[g][lane] : 0.f;
        float sp2 = (1.f-rl2)*sp + rl2*(ok ? S->sms[g][lane] : 0.f);
        float m2  = (1.f-rl2)*m  + rl2*(ok ? S->smm[g][lane] : 0.f);
        float score = ok ? m2 + logf(1.f/(sp2+EPSF)+EPSF) : -3.4e38f;
        float mx = rmax16(score);
        float ex = ok ? expf(score - mx) : 0.f;
        float sm = rsum16(ex);
        float ca = ex / sm;
        if (ok){ S->ssp[g][lane] = sp2*(1.f - 0.05f*ca*S->sval[g]) + EPSF; S->smaM[g][lane] = m2; }
      }
    }
    __syncthreads(); // S12
  }

  // ---- epilogue ----
  if (ht < 32){
    const bool ok = lane < 16;
    float sp = ok ? S->ssp[g][lane] : 0.f;
    float m  = ok ? S->smaM[g][lane] : 0.f;
    float score = ok ? m + logf(1.f/(sp+EPSF)+EPSF) : -3.4e38f;
    float mx = rmax16(score);
    float ex = ok ? expf(score - mx) : 0.f;
    float sm = rsum16(ex);
    float a  = ex / sm;
    if (ok) S->sal[g][lane] = a;
    float u   = rsum16(ok ? a*sp : 0.f);
    float ent = rsum16(ok ? -a*logf(fmaxf(a,1e-8f)) : 0.f);
    float mm2 = rmax16(ok ? m : -3.4e38f);
    float en  = mm2 + logf(rsum16(ok ? expf(m - mm2) : 0.f));
    float bv = ok ? a : -3.4e38f;
    int   bi = ok ? lane : 99;
    #pragma unroll
    for (int o = 8; o; o >>= 1){
      float ov = __shfl_xor_sync(0xffffffffu, bv, o);
      int   oi = __shfl_xor_sync(0xffffffffu, bi, o);
      if (ov > bv || (ov == bv && oi < bi)){ bv = ov; bi = oi; }
    }
    if (lane == 0){
      S->sciT[256][g] = u; S->sciT[258][g] = en; S->sciT[259][g] = ent; S->sidx[g] = bi;
    }
  }
  __syncthreads();
  {
    float core = 0.f;
    #pragma unroll
    for (int c = 0; c < 16; c++) core += S->sal[g][c] * S->sc[g][c][ht];
    float dv = 0.f;
    #pragma unroll
    for (int c = 0; c < 16; c++){ float dd = S->sc[g][c][ht] - core; dv += S->sal[g][c]*dd*dd; }
    dv = rsum32(dv);
    if (lane == 0) S->sred[g][wg][2] = dv;
    float strong = S->sc[g][S->sidx[g]][ht];
    S->sciT[ht][g] = core;
    S->sciT[128+ht][g] = strong;
  }
  __syncthreads();
  if (ht == 0)
    S->sciT[257][g] = (S->sred[g][0][2]+S->sred[g][1][2]+S->sred[g][2][2]+S->sred[g][3][2]) * (1.f/128.f);
  __syncthreads();
  {
    u64 aA[4] = {0,0,0,0}, aB[4] = {0,0,0,0};
    const int lo = isl * 16;
    #pragma unroll
    for (int r = 0; r < 16; r++){
      const int i = lo + r;
      ulonglong2 w = *(const ulonglong2*)&cw1[i*128 + j4*4];
      float4 x = *(const float4*)&S->sciT[i][0];
      u64 p0=pack2(x.x), p1=pack2(x.y), p2=pack2(x.z), p3=pack2(x.w);
      fma2(aA[0], p0, w.x); fma2(aB[0], p0, w.y);
      fma2(aA[1], p1, w.x); fma2(aB[1], p1, w.y);
      fma2(aA[2], p2, w.x); fma2(aB[2], p2, w.y);
      fma2(aA[3], p3, w.x); fma2(aB[3], p3, w.y);
    }
    if (isl < 4){
      const int i = 256 + isl;
      ulonglong2 w = *(const ulonglong2*)&cw1[i*128 + j4*4];
      float4 x = *(const float4*)&S->sciT[i][0];
      u64 p0=pack2(x.x), p1=pack2(x.y), p2=pack2(x.z), p3=pack2(x.w);
      fma2(aA[0], p0, w.x); fma2(aB[0], p0, w.y);
      fma2(aA[1], p1, w.x); fma2(aB[1], p1, w.y);
      fma2(aA[2], p2, w.x); fma2(aB[2], p2, w.y);
      fma2(aA[3], p3, w.x); fma2(aB[3], p3, w.y);
    }
    #pragma unroll
    for (int b2 = 0; b2 < 4; b2++){
      float2 l = unpack2(aA[b2]), h2 = unpack2(aB[b2]);
      *(float4*)&S->sbuf[isl][b2][j4*4] = make_float4(l.x, l.y, h2.x, h2.y);
    }
  }
  __syncthreads();
  {
    float s = cb1[ht];
    #pragma unroll
    for (int k = 0; k < 16; k++) s += S->sbuf[k][g][ht];
    S->sh1T[ht][g] = 0.5f * s * (1.f + erff(s * 0.70710678118654752440f));
  }
  __syncthreads();
  if (ht < 8){
    float s = cb2[ht];
    #pragma unroll 4
    for (int i = 0; i < 128; i++) s += S->sh1T[i][g] * cw2[i*8 + ht];
    out[b*8 + ht] = s;
  }
}

extern "C" void kernel_launch(void* const* d_in, const int* in_sizes, int n_in,
                              void* d_out, int out_size){
  (void)in_sizes; (void)n_in; (void)out_size;
  cudaFuncSetAttribute(cfrm_kernel, cudaFuncAttributeMaxDynamicSharedMemorySize, (int)sizeof(Smem));
  cfrm_kernel<<<32, 512, sizeof(Smem)>>>(
    (const int*)  d_in[0],  (const float*)d_in[1],  (const float*)d_in[2],  (const float*)d_in[3],
    (const float*)d_in[4],  (const float*)d_in[5],  (const float*)d_in[6],  (const float*)d_in[7],
    (const float*)d_in[8],  (const float*)d_in[9],  (const float*)d_in[10], (const float*)d_in[11],
    (const float*)d_in[12], (const float*)d_in[13], (const float*)d_in[14], (const float*)d_in[15],
    (const float*)d_in[16], (const float*)d_in[17], (const float*)d_in[18], (const float*)d_in[19],
    (const float*)d_in[20], (const float*)d_in[21], (const float*)d_in[22], (const float*)d_in[23],
    (const float*)d_in[24], (const float*)d_in[25], (const float*)d_in[26], (const float*)d_in[27],
    (float*)d_out);
}